// round 1
// baseline (speedup 1.0000x reference)
#include <cuda_runtime.h>

#define N_P   100000
#define N_G   40000
#define NE    1600000
#define NLBL  500000
#define D     64
#define F_GO  1000

// ---------------- scratch (static device allocations are allowed) ----------
__device__ float g_xp[2 * N_P * D];
__device__ float g_xg[2 * N_G * D];
__device__ float g_agg_p[N_P * D];
__device__ float g_agg_g[N_G * D];
__device__ int   g_deg_g[N_G];
__device__ int   g_deg_p[N_P];
__device__ int   g_rp_g[N_G + 1];
__device__ int   g_rp_p[N_P + 1];
__device__ int   g_cur_g[N_G];
__device__ int   g_cur_p[N_P];
__device__ int   g_csr_pg[NE];   // src protein ids grouped by dst go node
__device__ int   g_csr_gp[NE];   // src go ids grouped by dst protein node

// ---------------- CSR build --------------------------------------------------
__global__ void k_zero_deg(int* deg_g, int* deg_p) {
    int i = blockIdx.x * blockDim.x + threadIdx.x;
    if (i < N_G) deg_g[i] = 0;
    if (i < N_P) deg_p[i] = 0;
}

__global__ void k_count(const int* __restrict__ dpg, const int* __restrict__ dgp,
                        int* deg_g, int* deg_p) {
    int e = blockIdx.x * blockDim.x + threadIdx.x;
    if (e < NE) {
        atomicAdd(&deg_g[dpg[e]], 1);
        atomicAdd(&deg_p[dgp[e]], 1);
    }
}

// single-block chunked exclusive scan (n up to 100001)
__global__ void k_scan(const int* __restrict__ deg, int* __restrict__ rp,
                       int* __restrict__ cur, int n) {
    __shared__ int wsum[32];
    __shared__ int carry;
    int tid = threadIdx.x;
    if (tid == 0) carry = 0;
    __syncthreads();
    for (int base = 0; base < n; base += 1024) {
        int i = base + tid;
        int v = (i < n) ? deg[i] : 0;
        int x = v;
#pragma unroll
        for (int o = 1; o < 32; o <<= 1) {
            int y = __shfl_up_sync(0xffffffffu, x, o);
            if ((tid & 31) >= o) x += y;
        }
        if ((tid & 31) == 31) wsum[tid >> 5] = x;
        __syncthreads();
        if (tid < 32) {
            int w = wsum[tid];
#pragma unroll
            for (int o = 1; o < 32; o <<= 1) {
                int y = __shfl_up_sync(0xffffffffu, w, o);
                if (tid >= o) w += y;
            }
            wsum[tid] = w;
        }
        __syncthreads();
        int incl = x + ((tid >= 32) ? wsum[(tid >> 5) - 1] : 0);
        int excl = carry + incl - v;
        if (i < n) { rp[i] = excl; cur[i] = excl; }
        int total = wsum[31];
        __syncthreads();
        if (tid == 0) carry += total;
        __syncthreads();
    }
    if (tid == 0) rp[n] = carry;
}

__global__ void k_scatter(const int* __restrict__ src, const int* __restrict__ dst,
                          int* cur, int* csr) {
    int e = blockIdx.x * blockDim.x + threadIdx.x;
    if (e < NE) {
        int d = dst[e];
        int p = atomicAdd(&cur[d], 1);
        csr[p] = src[e];
    }
}

// ---------------- input embeddings ------------------------------------------
__global__ void k_init_xp(const float* __restrict__ pe, const int* __restrict__ nid,
                          float* __restrict__ xp) {
    int i = blockIdx.x * blockDim.x + threadIdx.x;   // over N_P * 16 float4s
    if (i >= N_P * 16) return;
    int r = i >> 4, q = i & 15;
    int n = nid[r];
    reinterpret_cast<float4*>(xp)[(size_t)r * 16 + q] =
        reinterpret_cast<const float4*>(pe + (size_t)n * D)[q];
}

// xg0 = go_x @ lin_W + lin_b + go_emb[go_nid]
// tiled fp32 GEMM: BM=64, BN=64, BK=32, 256 threads, 4x4 per thread
__global__ void k_init_xg(const float* __restrict__ go_x, const float* __restrict__ lin_W,
                          const float* __restrict__ lin_b, const float* __restrict__ go_emb,
                          const int* __restrict__ go_nid, float* __restrict__ xg) {
    __shared__ float As[64][36];  // [m][k], pad 36 (16B-aligned rows, conflict-free)
    __shared__ float Bs[32][64];  // [k][n]
    int tid = threadIdx.x;
    int tx = tid & 15, ty = tid >> 4;
    int m0 = blockIdx.x * 64;
    float c[4][4] = {};
    for (int k0 = 0; k0 < F_GO; k0 += 32) {
#pragma unroll
        for (int q = 0; q < 2; q++) {          // A tile 64x32
            int idx = tid + q * 256;
            int m = idx >> 3;
            int k4 = (idx & 7) << 2;
            int gk = k0 + k4;
            float4 v;
            if (gk + 3 < F_GO) {
                v = *reinterpret_cast<const float4*>(go_x + (size_t)(m0 + m) * F_GO + gk);
            } else {
                float t0 = (gk + 0 < F_GO) ? go_x[(size_t)(m0 + m) * F_GO + gk + 0] : 0.f;
                float t1 = (gk + 1 < F_GO) ? go_x[(size_t)(m0 + m) * F_GO + gk + 1] : 0.f;
                float t2 = (gk + 2 < F_GO) ? go_x[(size_t)(m0 + m) * F_GO + gk + 2] : 0.f;
                float t3 = (gk + 3 < F_GO) ? go_x[(size_t)(m0 + m) * F_GO + gk + 3] : 0.f;
                v = make_float4(t0, t1, t2, t3);
            }
            *reinterpret_cast<float4*>(&As[m][k4]) = v;
        }
#pragma unroll
        for (int q = 0; q < 2; q++) {          // B tile 32x64
            int idx = tid + q * 256;
            int kk = idx >> 4;
            int n4 = (idx & 15) << 2;
            int gk = k0 + kk;
            float4 v = make_float4(0.f, 0.f, 0.f, 0.f);
            if (gk < F_GO)
                v = *reinterpret_cast<const float4*>(lin_W + (size_t)gk * 64 + n4);
            *reinterpret_cast<float4*>(&Bs[kk][n4]) = v;
        }
        __syncthreads();
#pragma unroll
        for (int kk = 0; kk < 32; kk++) {
            float a0 = As[ty * 4 + 0][kk];
            float a1 = As[ty * 4 + 1][kk];
            float a2 = As[ty * 4 + 2][kk];
            float a3 = As[ty * 4 + 3][kk];
            float4 b = *reinterpret_cast<const float4*>(&Bs[kk][tx * 4]);
            c[0][0] += a0 * b.x; c[0][1] += a0 * b.y; c[0][2] += a0 * b.z; c[0][3] += a0 * b.w;
            c[1][0] += a1 * b.x; c[1][1] += a1 * b.y; c[1][2] += a1 * b.z; c[1][3] += a1 * b.w;
            c[2][0] += a2 * b.x; c[2][1] += a2 * b.y; c[2][2] += a2 * b.z; c[2][3] += a2 * b.w;
            c[3][0] += a3 * b.x; c[3][1] += a3 * b.y; c[3][2] += a3 * b.z; c[3][3] += a3 * b.w;
        }
        __syncthreads();
    }
    float4 bias = *reinterpret_cast<const float4*>(lin_b + tx * 4);
#pragma unroll
    for (int i = 0; i < 4; i++) {
        int row = m0 + ty * 4 + i;               // grid covers N_G exactly
        int gn = go_nid[row];
        float4 emb = *reinterpret_cast<const float4*>(go_emb + (size_t)gn * D + tx * 4);
        float4 o;
        o.x = c[i][0] + bias.x + emb.x;
        o.y = c[i][1] + bias.y + emb.y;
        o.z = c[i][2] + bias.z + emb.z;
        o.w = c[i][3] + bias.w + emb.w;
        *reinterpret_cast<float4*>(xg + (size_t)row * D + tx * 4) = o;
    }
}

// ---------------- mean aggregation: warp per destination node ----------------
__global__ void k_aggregate(const float* __restrict__ xs, const int* __restrict__ rp,
                            const int* __restrict__ csr, float* __restrict__ out, int n) {
    int warp = (blockIdx.x * blockDim.x + threadIdx.x) >> 5;
    if (warp >= n) return;
    int lane = threadIdx.x & 31;
    int s = rp[warp], e = rp[warp + 1];
    float accx = 0.f, accy = 0.f;
    int i = s;
    for (; i + 4 <= e; i += 4) {
        int s0 = csr[i + 0], s1 = csr[i + 1], s2 = csr[i + 2], s3 = csr[i + 3];
        float2 v0 = *reinterpret_cast<const float2*>(xs + (size_t)s0 * D + lane * 2);
        float2 v1 = *reinterpret_cast<const float2*>(xs + (size_t)s1 * D + lane * 2);
        float2 v2 = *reinterpret_cast<const float2*>(xs + (size_t)s2 * D + lane * 2);
        float2 v3 = *reinterpret_cast<const float2*>(xs + (size_t)s3 * D + lane * 2);
        accx += (v0.x + v1.x) + (v2.x + v3.x);
        accy += (v0.y + v1.y) + (v2.y + v3.y);
    }
    for (; i < e; i++) {
        int s0 = csr[i];
        float2 v = *reinterpret_cast<const float2*>(xs + (size_t)s0 * D + lane * 2);
        accx += v.x; accy += v.y;
    }
    float inv = (e > s) ? 1.0f / (float)(e - s) : 0.f;
    *reinterpret_cast<float2*>(out + (size_t)warp * D + lane * 2) =
        make_float2(accx * inv, accy * inv);
}

// ---------------- node update: out = agg@Wl + bl + x@Wr (+relu) --------------
// BM=64 nodes, K=64 per pass (two passes: Wl then Wr), 256 threads, 4x4/thread
__global__ void k_update(const float* __restrict__ agg, const float* __restrict__ x,
                         const float* __restrict__ Wl, const float* __restrict__ bl,
                         const float* __restrict__ Wr, float* __restrict__ out,
                         int n, int do_relu) {
    __shared__ float As[64][68];   // pad 68: 16B-aligned rows
    __shared__ float Bs[64][64];
    int tid = threadIdx.x;
    int tx = tid & 15, ty = tid >> 4;
    int m0 = blockIdx.x * 64;
    float c[4][4] = {};
#pragma unroll
    for (int pass = 0; pass < 2; pass++) {
        const float* A = pass ? x : agg;
        const float* B = pass ? Wr : Wl;
        __syncthreads();
#pragma unroll
        for (int q = 0; q < 4; q++) {   // A tile 64x64
            int idx = tid + q * 256;
            int m = idx >> 4;
            int k4 = (idx & 15) << 2;
            int row = m0 + m;
            float4 v = make_float4(0.f, 0.f, 0.f, 0.f);
            if (row < n)
                v = *reinterpret_cast<const float4*>(A + (size_t)row * D + k4);
            *reinterpret_cast<float4*>(&As[m][k4]) = v;
        }
#pragma unroll
        for (int q = 0; q < 4; q++) {   // B 64x64
            int idx = tid + q * 256;
            int k = idx >> 4;
            int n4 = (idx & 15) << 2;
            *reinterpret_cast<float4*>(&Bs[k][n4]) =
                *reinterpret_cast<const float4*>(B + k * 64 + n4);
        }
        __syncthreads();
#pragma unroll
        for (int kk = 0; kk < 64; kk++) {
            float a0 = As[ty * 4 + 0][kk];
            float a1 = As[ty * 4 + 1][kk];
            float a2 = As[ty * 4 + 2][kk];
            float a3 = As[ty * 4 + 3][kk];
            float4 b = *reinterpret_cast<const float4*>(&Bs[kk][tx * 4]);
            c[0][0] += a0 * b.x; c[0][1] += a0 * b.y; c[0][2] += a0 * b.z; c[0][3] += a0 * b.w;
            c[1][0] += a1 * b.x; c[1][1] += a1 * b.y; c[1][2] += a1 * b.z; c[1][3] += a1 * b.w;
            c[2][0] += a2 * b.x; c[2][1] += a2 * b.y; c[2][2] += a2 * b.z; c[2][3] += a2 * b.w;
            c[3][0] += a3 * b.x; c[3][1] += a3 * b.y; c[3][2] += a3 * b.z; c[3][3] += a3 * b.w;
        }
    }
    float4 bias = *reinterpret_cast<const float4*>(bl + tx * 4);
#pragma unroll
    for (int i = 0; i < 4; i++) {
        int row = m0 + ty * 4 + i;
        if (row < n) {
            float4 o;
            o.x = c[i][0] + bias.x;
            o.y = c[i][1] + bias.y;
            o.z = c[i][2] + bias.z;
            o.w = c[i][3] + bias.w;
            if (do_relu) {
                o.x = fmaxf(o.x, 0.f); o.y = fmaxf(o.y, 0.f);
                o.z = fmaxf(o.z, 0.f); o.w = fmaxf(o.w, 0.f);
            }
            *reinterpret_cast<float4*>(out + (size_t)row * D + tx * 4) = o;
        }
    }
}

// ---------------- classifier: warp per label edge ----------------------------
__global__ void k_classifier(const int* __restrict__ ls, const int* __restrict__ ld,
                             const float* __restrict__ xp, const float* __restrict__ xg,
                             float* __restrict__ out, int n) {
    int w = (blockIdx.x * blockDim.x + threadIdx.x) >> 5;
    if (w >= n) return;
    int lane = threadIdx.x & 31;
    int a = ls[w], b = ld[w];
    float2 va = *reinterpret_cast<const float2*>(xp + (size_t)a * D + lane * 2);
    float2 vb = *reinterpret_cast<const float2*>(xg + (size_t)b * D + lane * 2);
    float s = va.x * vb.x + va.y * vb.y;
#pragma unroll
    for (int o = 16; o; o >>= 1) s += __shfl_down_sync(0xffffffffu, s, o);
    if (lane == 0) out[w] = s;
}

// ---------------- driver -----------------------------------------------------
extern "C" void kernel_launch(void* const* d_in, const int* in_sizes, int n_in,
                              void* d_out, int out_size) {
    const float* go_x        = (const float*)d_in[0];
    const float* protein_emb = (const float*)d_in[1];
    const float* go_emb      = (const float*)d_in[2];
    const float* lin_W       = (const float*)d_in[3];
    const float* lin_b       = (const float*)d_in[4];
    const float* Wl          = (const float*)d_in[5];
    const float* bl          = (const float*)d_in[6];
    const float* Wr          = (const float*)d_in[7];
    const int*   protein_nid = (const int*)d_in[8];
    const int*   go_nid      = (const int*)d_in[9];
    const int*   src_pg      = (const int*)d_in[10];
    const int*   dst_pg      = (const int*)d_in[11];
    const int*   src_gp      = (const int*)d_in[12];
    const int*   dst_gp      = (const int*)d_in[13];
    const int*   label_src   = (const int*)d_in[14];
    const int*   label_dst   = (const int*)d_in[15];
    float* out = (float*)d_out;

    float *xp, *xg, *agg_p, *agg_g;
    int *deg_g, *deg_p, *rp_g, *rp_p, *cur_g, *cur_p, *csr_pg, *csr_gp;
    cudaGetSymbolAddress((void**)&xp,     g_xp);
    cudaGetSymbolAddress((void**)&xg,     g_xg);
    cudaGetSymbolAddress((void**)&agg_p,  g_agg_p);
    cudaGetSymbolAddress((void**)&agg_g,  g_agg_g);
    cudaGetSymbolAddress((void**)&deg_g,  g_deg_g);
    cudaGetSymbolAddress((void**)&deg_p,  g_deg_p);
    cudaGetSymbolAddress((void**)&rp_g,   g_rp_g);
    cudaGetSymbolAddress((void**)&rp_p,   g_rp_p);
    cudaGetSymbolAddress((void**)&cur_g,  g_cur_g);
    cudaGetSymbolAddress((void**)&cur_p,  g_cur_p);
    cudaGetSymbolAddress((void**)&csr_pg, g_csr_pg);
    cudaGetSymbolAddress((void**)&csr_gp, g_csr_gp);

    float* xp_buf[2] = { xp, xp + (size_t)N_P * D };
    float* xg_buf[2] = { xg, xg + (size_t)N_G * D };

    // CSR build (rebuilt every call: identical work, deterministic up to fp-sum order)
    k_zero_deg<<<(N_P + 255) / 256, 256>>>(deg_g, deg_p);
    k_count<<<(NE + 255) / 256, 256>>>(dst_pg, dst_gp, deg_g, deg_p);
    k_scan<<<1, 1024>>>(deg_g, rp_g, cur_g, N_G);
    k_scan<<<1, 1024>>>(deg_p, rp_p, cur_p, N_P);
    k_scatter<<<(NE + 255) / 256, 256>>>(src_pg, dst_pg, cur_g, csr_pg);
    k_scatter<<<(NE + 255) / 256, 256>>>(src_gp, dst_gp, cur_p, csr_gp);

    // input embeddings
    k_init_xp<<<(N_P * 16 + 255) / 256, 256>>>(protein_emb, protein_nid, xp_buf[0]);
    k_init_xg<<<N_G / 64, 256>>>(go_x, lin_W, lin_b, go_emb, go_nid, xg_buf[0]);

    int cur = 0;
    for (int l = 0; l < 3; l++) {
        k_aggregate<<<(N_G + 7) / 8, 256>>>(xp_buf[cur], rp_g, csr_pg, agg_g, N_G);
        k_aggregate<<<(N_P + 7) / 8, 256>>>(xg_buf[cur], rp_p, csr_gp, agg_p, N_P);
        int relu = (l < 2) ? 1 : 0;
        k_update<<<(N_G + 63) / 64, 256>>>(agg_g, xg_buf[cur],
                                           Wl + (size_t)(l * 2 + 0) * 64 * 64,
                                           bl + (size_t)(l * 2 + 0) * 64,
                                           Wr + (size_t)(l * 2 + 0) * 64 * 64,
                                           xg_buf[1 - cur], N_G, relu);
        k_update<<<(N_P + 63) / 64, 256>>>(agg_p, xp_buf[cur],
                                           Wl + (size_t)(l * 2 + 1) * 64 * 64,
                                           bl + (size_t)(l * 2 + 1) * 64,
                                           Wr + (size_t)(l * 2 + 1) * 64 * 64,
                                           xp_buf[1 - cur], N_P, relu);
        cur ^= 1;
    }

    k_classifier<<<(NLBL + 7) / 8, 256>>>(label_src, label_dst,
                                          xp_buf[cur], xg_buf[cur], out, NLBL);
}

// round 2
// speedup vs baseline: 1.2032x; 1.2032x over previous
#include <cuda_runtime.h>

#define N_P   100000
#define N_G   40000
#define NE    1600000
#define NLBL  500000
#define D     64
#define F_GO  1000

#define CHUNK  4096
#define NBLK_G ((N_G + CHUNK - 1) / CHUNK)   // 10
#define NBLK_P ((N_P + CHUNK - 1) / CHUNK)   // 25

typedef unsigned long long u64;

// ---------------- scratch ----------------------------------------------------
__device__ float g_xp[2 * N_P * D];
__device__ float g_xg[2 * N_G * D];
__device__ float g_agg_p[N_P * D];
__device__ float g_agg_g[N_G * D];
__device__ int   g_deg_g[N_G];
__device__ int   g_deg_p[N_P];
__device__ int   g_rp_g[N_G + 1];
__device__ int   g_rp_p[N_P + 1];
__device__ int   g_cur_g[N_G];
__device__ int   g_cur_p[N_P];
__device__ int   g_csr_pg[NE];
__device__ int   g_csr_gp[NE];
__device__ int   g_bsum_g[32];
__device__ int   g_bsum_p[32];

// ---------------- packed f32x2 helpers ---------------------------------------
__device__ __forceinline__ u64 pack2s(float x) {
    u64 r; asm("mov.b64 %0,{%1,%1};" : "=l"(r) : "f"(x)); return r;
}
__device__ __forceinline__ u64 ffma2(u64 a, u64 b, u64 c) {
    u64 d; asm("fma.rn.f32x2 %0,%1,%2,%3;" : "=l"(d) : "l"(a), "l"(b), "l"(c)); return d;
}
__device__ __forceinline__ float2 unpack2(u64 v) {
    float2 f; asm("mov.b64 {%0,%1},%2;" : "=f"(f.x), "=f"(f.y) : "l"(v)); return f;
}

// ---------------- CSR build --------------------------------------------------
__global__ void k_zero_deg(int* deg_g, int* deg_p) {
    int i = blockIdx.x * blockDim.x + threadIdx.x;
    if (i < N_G) deg_g[i] = 0;
    if (i < N_P) deg_p[i] = 0;
}

__global__ void k_count(const int* __restrict__ dpg, const int* __restrict__ dgp,
                        int* deg_g, int* deg_p) {
    int e = blockIdx.x * blockDim.x + threadIdx.x;
    if (e < NE) {
        atomicAdd(&deg_g[dpg[e]], 1);
        atomicAdd(&deg_p[dgp[e]], 1);
    }
}

// pass 1: per-block local exclusive scan (stored in rp), block totals to bsum
__global__ void k_scan_local(const int* __restrict__ deg_g, int* __restrict__ rp_g,
                             int* __restrict__ bsum_g,
                             const int* __restrict__ deg_p, int* __restrict__ rp_p,
                             int* __restrict__ bsum_p) {
    __shared__ int wsum[32];
    int b = blockIdx.x;
    const int* deg; int* rp; int* bsum; int n, cb;
    if (b < NBLK_G) { deg = deg_g; rp = rp_g; bsum = bsum_g; n = N_G; cb = b; }
    else            { deg = deg_p; rp = rp_p; bsum = bsum_p; n = N_P; cb = b - NBLK_G; }
    int tid = threadIdx.x;
    int idx = cb * CHUNK + tid * 4;
    int v0 = 0, v1 = 0, v2 = 0, v3 = 0;
    if (idx + 3 < n) {
        int4 t = *reinterpret_cast<const int4*>(deg + idx);
        v0 = t.x; v1 = t.y; v2 = t.z; v3 = t.w;
    } else {
        if (idx + 0 < n) v0 = deg[idx + 0];
        if (idx + 1 < n) v1 = deg[idx + 1];
        if (idx + 2 < n) v2 = deg[idx + 2];
        if (idx + 3 < n) v3 = deg[idx + 3];
    }
    int t = v0 + v1 + v2 + v3;
    int x = t;
#pragma unroll
    for (int o = 1; o < 32; o <<= 1) {
        int y = __shfl_up_sync(0xffffffffu, x, o);
        if ((tid & 31) >= o) x += y;
    }
    if ((tid & 31) == 31) wsum[tid >> 5] = x;
    __syncthreads();
    if (tid < 32) {
        int w = wsum[tid];
#pragma unroll
        for (int o = 1; o < 32; o <<= 1) {
            int y = __shfl_up_sync(0xffffffffu, w, o);
            if (tid >= o) w += y;
        }
        wsum[tid] = w;
    }
    __syncthreads();
    int excl = (x - t) + ((tid >= 32) ? wsum[(tid >> 5) - 1] : 0);
    int r0 = excl, r1 = r0 + v0, r2 = r1 + v1, r3 = r2 + v2;
    if (idx + 3 < n) {
        *reinterpret_cast<int4*>(rp + idx) = make_int4(r0, r1, r2, r3);
    } else {
        if (idx + 0 < n) rp[idx + 0] = r0;
        if (idx + 1 < n) rp[idx + 1] = r1;
        if (idx + 2 < n) rp[idx + 2] = r2;
        if (idx + 3 < n) rp[idx + 3] = r3;
    }
    if (tid == 0) bsum[cb] = wsum[31];
}

// pass 2: tiny serial scan of block sums; also writes rp[n]
__global__ void k_scan_mid(int* bsum_g, int* bsum_p, int* rp_g, int* rp_p) {
    if (threadIdx.x == 0) {
        int run = 0;
        for (int i = 0; i < NBLK_G; i++) { int t = bsum_g[i]; bsum_g[i] = run; run += t; }
        rp_g[N_G] = run;
    } else if (threadIdx.x == 1) {
        int run = 0;
        for (int i = 0; i < NBLK_P; i++) { int t = bsum_p[i]; bsum_p[i] = run; run += t; }
        rp_p[N_P] = run;
    }
}

// pass 3: add block offsets, mirror into cur
__global__ void k_scan_fix(int* __restrict__ rp_g, int* __restrict__ cur_g,
                           const int* __restrict__ bsum_g,
                           int* __restrict__ rp_p, int* __restrict__ cur_p,
                           const int* __restrict__ bsum_p) {
    int b = blockIdx.x;
    int* rp; int* cur; const int* bsum; int n, cb;
    if (b < NBLK_G) { rp = rp_g; cur = cur_g; bsum = bsum_g; n = N_G; cb = b; }
    else            { rp = rp_p; cur = cur_p; bsum = bsum_p; n = N_P; cb = b - NBLK_G; }
    int off = bsum[cb];
    int idx = cb * CHUNK + threadIdx.x * 4;
    if (idx + 3 < n) {
        int4 t = *reinterpret_cast<int4*>(rp + idx);
        t.x += off; t.y += off; t.z += off; t.w += off;
        *reinterpret_cast<int4*>(rp + idx)  = t;
        *reinterpret_cast<int4*>(cur + idx) = t;
    } else {
        for (int j = 0; j < 4; j++)
            if (idx + j < n) { int v = rp[idx + j] + off; rp[idx + j] = v; cur[idx + j] = v; }
    }
}

__global__ void k_scatter(const int* __restrict__ src, const int* __restrict__ dst,
                          int* cur, int* csr) {
    int e = blockIdx.x * blockDim.x + threadIdx.x;
    if (e < NE) {
        int d = dst[e];
        int p = atomicAdd(&cur[d], 1);
        csr[p] = src[e];
    }
}

// ---------------- input embeddings ------------------------------------------
__global__ void k_init_xp(const float* __restrict__ pe, const int* __restrict__ nid,
                          float* __restrict__ xp) {
    int i = blockIdx.x * blockDim.x + threadIdx.x;
    if (i >= N_P * 16) return;
    int r = i >> 4, q = i & 15;
    int n = nid[r];
    reinterpret_cast<float4*>(xp)[(size_t)r * 16 + q] =
        reinterpret_cast<const float4*>(pe + (size_t)n * D)[q];
}

// xg0 = go_x @ lin_W + lin_b + go_emb[go_nid] ; packed FFMA2 inner loop
__global__ void k_init_xg(const float* __restrict__ go_x, const float* __restrict__ lin_W,
                          const float* __restrict__ lin_b, const float* __restrict__ go_emb,
                          const int* __restrict__ go_nid, float* __restrict__ xg) {
    __shared__ float As[64][36];
    __shared__ float Bs[32][64];
    int tid = threadIdx.x;
    int tx = tid & 15, ty = tid >> 4;
    int m0 = blockIdx.x * 64;
    u64 cc[4][2] = {};
    for (int k0 = 0; k0 < F_GO; k0 += 32) {
#pragma unroll
        for (int q = 0; q < 2; q++) {
            int idx = tid + q * 256;
            int m = idx >> 3;
            int k4 = (idx & 7) << 2;
            int gk = k0 + k4;
            float4 v;
            if (gk + 3 < F_GO) {
                v = *reinterpret_cast<const float4*>(go_x + (size_t)(m0 + m) * F_GO + gk);
            } else {
                float t0 = (gk + 0 < F_GO) ? go_x[(size_t)(m0 + m) * F_GO + gk + 0] : 0.f;
                float t1 = (gk + 1 < F_GO) ? go_x[(size_t)(m0 + m) * F_GO + gk + 1] : 0.f;
                float t2 = (gk + 2 < F_GO) ? go_x[(size_t)(m0 + m) * F_GO + gk + 2] : 0.f;
                float t3 = (gk + 3 < F_GO) ? go_x[(size_t)(m0 + m) * F_GO + gk + 3] : 0.f;
                v = make_float4(t0, t1, t2, t3);
            }
            *reinterpret_cast<float4*>(&As[m][k4]) = v;
        }
#pragma unroll
        for (int q = 0; q < 2; q++) {
            int idx = tid + q * 256;
            int kk = idx >> 4;
            int n4 = (idx & 15) << 2;
            int gk = k0 + kk;
            float4 v = make_float4(0.f, 0.f, 0.f, 0.f);
            if (gk < F_GO)
                v = *reinterpret_cast<const float4*>(lin_W + (size_t)gk * 64 + n4);
            *reinterpret_cast<float4*>(&Bs[kk][n4]) = v;
        }
        __syncthreads();
#pragma unroll
        for (int kk = 0; kk < 32; kk++) {
            const u64* bp = reinterpret_cast<const u64*>(&Bs[kk][tx * 4]);
            u64 b01 = bp[0], b23 = bp[1];
            u64 a0 = pack2s(As[ty * 4 + 0][kk]);
            u64 a1 = pack2s(As[ty * 4 + 1][kk]);
            u64 a2 = pack2s(As[ty * 4 + 2][kk]);
            u64 a3 = pack2s(As[ty * 4 + 3][kk]);
            cc[0][0] = ffma2(a0, b01, cc[0][0]); cc[0][1] = ffma2(a0, b23, cc[0][1]);
            cc[1][0] = ffma2(a1, b01, cc[1][0]); cc[1][1] = ffma2(a1, b23, cc[1][1]);
            cc[2][0] = ffma2(a2, b01, cc[2][0]); cc[2][1] = ffma2(a2, b23, cc[2][1]);
            cc[3][0] = ffma2(a3, b01, cc[3][0]); cc[3][1] = ffma2(a3, b23, cc[3][1]);
        }
        __syncthreads();
    }
    float4 bias = *reinterpret_cast<const float4*>(lin_b + tx * 4);
#pragma unroll
    for (int i = 0; i < 4; i++) {
        int row = m0 + ty * 4 + i;
        int gn = go_nid[row];
        float4 emb = *reinterpret_cast<const float4*>(go_emb + (size_t)gn * D + tx * 4);
        float2 lo = unpack2(cc[i][0]);
        float2 hi = unpack2(cc[i][1]);
        float4 o;
        o.x = lo.x + bias.x + emb.x;
        o.y = lo.y + bias.y + emb.y;
        o.z = hi.x + bias.z + emb.z;
        o.w = hi.y + bias.w + emb.w;
        *reinterpret_cast<float4*>(xg + (size_t)row * D + tx * 4) = o;
    }
}

// ---------------- mean aggregation (both edge types, one launch) -------------
__global__ void k_aggregate_both(const float* __restrict__ xp, const int* __restrict__ rp_g,
                                 const int* __restrict__ csr_pg, float* __restrict__ agg_g,
                                 const float* __restrict__ xg, const int* __restrict__ rp_p,
                                 const int* __restrict__ csr_gp, float* __restrict__ agg_p) {
    int warp = (blockIdx.x * blockDim.x + threadIdx.x) >> 5;
    const float* xs; const int* rp; const int* csr; float* out; int node;
    if (warp < N_G) { xs = xp; rp = rp_g; csr = csr_pg; out = agg_g; node = warp; }
    else if (warp < N_G + N_P) { xs = xg; rp = rp_p; csr = csr_gp; out = agg_p; node = warp - N_G; }
    else return;
    int lane = threadIdx.x & 31;
    int s = rp[node], e = rp[node + 1];
    float accx = 0.f, accy = 0.f;
    int i = s;
    for (; i + 4 <= e; i += 4) {
        int s0 = csr[i + 0], s1 = csr[i + 1], s2 = csr[i + 2], s3 = csr[i + 3];
        float2 v0 = *reinterpret_cast<const float2*>(xs + (size_t)s0 * D + lane * 2);
        float2 v1 = *reinterpret_cast<const float2*>(xs + (size_t)s1 * D + lane * 2);
        float2 v2 = *reinterpret_cast<const float2*>(xs + (size_t)s2 * D + lane * 2);
        float2 v3 = *reinterpret_cast<const float2*>(xs + (size_t)s3 * D + lane * 2);
        accx += (v0.x + v1.x) + (v2.x + v3.x);
        accy += (v0.y + v1.y) + (v2.y + v3.y);
    }
    for (; i < e; i++) {
        int s0 = csr[i];
        float2 v = *reinterpret_cast<const float2*>(xs + (size_t)s0 * D + lane * 2);
        accx += v.x; accy += v.y;
    }
    float inv = (e > s) ? 1.0f / (float)(e - s) : 0.f;
    *reinterpret_cast<float2*>(out + (size_t)node * D + lane * 2) =
        make_float2(accx * inv, accy * inv);
}

// ---------------- node update (both node types, one launch, FFMA2) -----------
#define BLOCKS_UG ((N_G + 63) / 64)
#define BLOCKS_UP ((N_P + 63) / 64)

__global__ void k_update_both(const float* __restrict__ agg_g, const float* __restrict__ xg,
                              const float* __restrict__ Wgl, const float* __restrict__ bg,
                              const float* __restrict__ Wgr, float* __restrict__ outg,
                              const float* __restrict__ agg_p, const float* __restrict__ xp,
                              const float* __restrict__ Wpl, const float* __restrict__ bp_,
                              const float* __restrict__ Wpr, float* __restrict__ outp,
                              int do_relu) {
    __shared__ float As[64][68];
    __shared__ float Bs[64][64];
    int tid = threadIdx.x;
    int tx = tid & 15, ty = tid >> 4;
    const float *Agg, *X, *WL, *WR, *bias_p; float* out; int n, m0;
    if (blockIdx.x < BLOCKS_UG) {
        Agg = agg_g; X = xg; WL = Wgl; WR = Wgr; bias_p = bg; out = outg;
        n = N_G; m0 = blockIdx.x * 64;
    } else {
        Agg = agg_p; X = xp; WL = Wpl; WR = Wpr; bias_p = bp_; out = outp;
        n = N_P; m0 = (blockIdx.x - BLOCKS_UG) * 64;
    }
    u64 cc[4][2] = {};
#pragma unroll
    for (int pass = 0; pass < 2; pass++) {
        const float* A = pass ? X : Agg;
        const float* B = pass ? WR : WL;
        __syncthreads();
#pragma unroll
        for (int q = 0; q < 4; q++) {
            int idx = tid + q * 256;
            int m = idx >> 4;
            int k4 = (idx & 15) << 2;
            int row = m0 + m;
            float4 v = make_float4(0.f, 0.f, 0.f, 0.f);
            if (row < n)
                v = *reinterpret_cast<const float4*>(A + (size_t)row * D + k4);
            *reinterpret_cast<float4*>(&As[m][k4]) = v;
        }
#pragma unroll
        for (int q = 0; q < 4; q++) {
            int idx = tid + q * 256;
            int k = idx >> 4;
            int n4 = (idx & 15) << 2;
            *reinterpret_cast<float4*>(&Bs[k][n4]) =
                *reinterpret_cast<const float4*>(B + k * 64 + n4);
        }
        __syncthreads();
#pragma unroll
        for (int kk = 0; kk < 64; kk++) {
            const u64* bp2 = reinterpret_cast<const u64*>(&Bs[kk][tx * 4]);
            u64 b01 = bp2[0], b23 = bp2[1];
            u64 a0 = pack2s(As[ty * 4 + 0][kk]);
            u64 a1 = pack2s(As[ty * 4 + 1][kk]);
            u64 a2 = pack2s(As[ty * 4 + 2][kk]);
            u64 a3 = pack2s(As[ty * 4 + 3][kk]);
            cc[0][0] = ffma2(a0, b01, cc[0][0]); cc[0][1] = ffma2(a0, b23, cc[0][1]);
            cc[1][0] = ffma2(a1, b01, cc[1][0]); cc[1][1] = ffma2(a1, b23, cc[1][1]);
            cc[2][0] = ffma2(a2, b01, cc[2][0]); cc[2][1] = ffma2(a2, b23, cc[2][1]);
            cc[3][0] = ffma2(a3, b01, cc[3][0]); cc[3][1] = ffma2(a3, b23, cc[3][1]);
        }
    }
    float4 bias = *reinterpret_cast<const float4*>(bias_p + tx * 4);
#pragma unroll
    for (int i = 0; i < 4; i++) {
        int row = m0 + ty * 4 + i;
        if (row < n) {
            float2 lo = unpack2(cc[i][0]);
            float2 hi = unpack2(cc[i][1]);
            float4 o;
            o.x = lo.x + bias.x;
            o.y = lo.y + bias.y;
            o.z = hi.x + bias.z;
            o.w = hi.y + bias.w;
            if (do_relu) {
                o.x = fmaxf(o.x, 0.f); o.y = fmaxf(o.y, 0.f);
                o.z = fmaxf(o.z, 0.f); o.w = fmaxf(o.w, 0.f);
            }
            *reinterpret_cast<float4*>(out + (size_t)row * D + tx * 4) = o;
        }
    }
}

// ---------------- classifier -------------------------------------------------
__global__ void k_classifier(const int* __restrict__ ls, const int* __restrict__ ld,
                             const float* __restrict__ xp, const float* __restrict__ xg,
                             float* __restrict__ out, int n) {
    int w = (blockIdx.x * blockDim.x + threadIdx.x) >> 5;
    if (w >= n) return;
    int lane = threadIdx.x & 31;
    int a = ls[w], b = ld[w];
    float2 va = *reinterpret_cast<const float2*>(xp + (size_t)a * D + lane * 2);
    float2 vb = *reinterpret_cast<const float2*>(xg + (size_t)b * D + lane * 2);
    float s = va.x * vb.x + va.y * vb.y;
#pragma unroll
    for (int o = 16; o; o >>= 1) s += __shfl_down_sync(0xffffffffu, s, o);
    if (lane == 0) out[w] = s;
}

// ---------------- driver -----------------------------------------------------
extern "C" void kernel_launch(void* const* d_in, const int* in_sizes, int n_in,
                              void* d_out, int out_size) {
    const float* go_x        = (const float*)d_in[0];
    const float* protein_emb = (const float*)d_in[1];
    const float* go_emb      = (const float*)d_in[2];
    const float* lin_W       = (const float*)d_in[3];
    const float* lin_b       = (const float*)d_in[4];
    const float* Wl          = (const float*)d_in[5];
    const float* bl          = (const float*)d_in[6];
    const float* Wr          = (const float*)d_in[7];
    const int*   protein_nid = (const int*)d_in[8];
    const int*   go_nid      = (const int*)d_in[9];
    const int*   src_pg      = (const int*)d_in[10];
    const int*   dst_pg      = (const int*)d_in[11];
    const int*   src_gp      = (const int*)d_in[12];
    const int*   dst_gp      = (const int*)d_in[13];
    const int*   label_src   = (const int*)d_in[14];
    const int*   label_dst   = (const int*)d_in[15];
    float* out = (float*)d_out;

    float *xp, *xg, *agg_p, *agg_g;
    int *deg_g, *deg_p, *rp_g, *rp_p, *cur_g, *cur_p, *csr_pg, *csr_gp, *bsum_g, *bsum_p;
    cudaGetSymbolAddress((void**)&xp,     g_xp);
    cudaGetSymbolAddress((void**)&xg,     g_xg);
    cudaGetSymbolAddress((void**)&agg_p,  g_agg_p);
    cudaGetSymbolAddress((void**)&agg_g,  g_agg_g);
    cudaGetSymbolAddress((void**)&deg_g,  g_deg_g);
    cudaGetSymbolAddress((void**)&deg_p,  g_deg_p);
    cudaGetSymbolAddress((void**)&rp_g,   g_rp_g);
    cudaGetSymbolAddress((void**)&rp_p,   g_rp_p);
    cudaGetSymbolAddress((void**)&cur_g,  g_cur_g);
    cudaGetSymbolAddress((void**)&cur_p,  g_cur_p);
    cudaGetSymbolAddress((void**)&csr_pg, g_csr_pg);
    cudaGetSymbolAddress((void**)&csr_gp, g_csr_gp);
    cudaGetSymbolAddress((void**)&bsum_g, g_bsum_g);
    cudaGetSymbolAddress((void**)&bsum_p, g_bsum_p);

    float* xp_buf[2] = { xp, xp + (size_t)N_P * D };
    float* xg_buf[2] = { xg, xg + (size_t)N_G * D };

    // CSR build
    k_zero_deg<<<(N_P + 255) / 256, 256>>>(deg_g, deg_p);
    k_count<<<(NE + 255) / 256, 256>>>(dst_pg, dst_gp, deg_g, deg_p);
    k_scan_local<<<NBLK_G + NBLK_P, 1024>>>(deg_g, rp_g, bsum_g, deg_p, rp_p, bsum_p);
    k_scan_mid<<<1, 32>>>(bsum_g, bsum_p, rp_g, rp_p);
    k_scan_fix<<<NBLK_G + NBLK_P, 1024>>>(rp_g, cur_g, bsum_g, rp_p, cur_p, bsum_p);
    k_scatter<<<(NE + 255) / 256, 256>>>(src_pg, dst_pg, cur_g, csr_pg);
    k_scatter<<<(NE + 255) / 256, 256>>>(src_gp, dst_gp, cur_p, csr_gp);

    // input embeddings
    k_init_xp<<<(N_P * 16 + 255) / 256, 256>>>(protein_emb, protein_nid, xp_buf[0]);
    k_init_xg<<<N_G / 64, 256>>>(go_x, lin_W, lin_b, go_emb, go_nid, xg_buf[0]);

    int cur = 0;
    for (int l = 0; l < 3; l++) {
        int agg_warps = N_G + N_P;
        k_aggregate_both<<<(agg_warps * 32 + 255) / 256, 256>>>(
            xp_buf[cur], rp_g, csr_pg, agg_g,
            xg_buf[cur], rp_p, csr_gp, agg_p);
        int relu = (l < 2) ? 1 : 0;
        k_update_both<<<BLOCKS_UG + BLOCKS_UP, 256>>>(
            agg_g, xg_buf[cur],
            Wl + (size_t)(l * 2 + 0) * 64 * 64, bl + (size_t)(l * 2 + 0) * 64,
            Wr + (size_t)(l * 2 + 0) * 64 * 64, xg_buf[1 - cur],
            agg_p, xp_buf[cur],
            Wl + (size_t)(l * 2 + 1) * 64 * 64, bl + (size_t)(l * 2 + 1) * 64,
            Wr + (size_t)(l * 2 + 1) * 64 * 64, xp_buf[1 - cur],
            relu);
        cur ^= 1;
    }

    k_classifier<<<(NLBL + 7) / 8, 256>>>(label_src, label_dst,
                                          xp_buf[cur], xg_buf[cur], out, NLBL);
}